// round 6
// baseline (speedup 1.0000x reference)
#include <cuda_runtime.h>
#include <cstdint>

// out[n] = w_mp * sum_{e : dst[e]==n} ew[e] * x[src[e]]
// x: [N,32] f32, edge_index: [2,E] int32, ew: [E] f32, w_mp: [1] f32
//
// CSR-on-the-fly pipeline: hist -> scan -> permute -> per-node gather.
// No atomics on the 128B feature path (was the REDG-issue bottleneck).

#define N_MAX 131072
#define E_MAX 1800000
#define SCAN_T 1024

__device__ int g_cnt[N_MAX];
__device__ int g_off[N_MAX + 1];
__device__ int g_cur[N_MAX];
__device__ int g_bsum[256];
__device__ unsigned long long g_rec[E_MAX];   // (bits(ew) << 32) | src

// ---------- K1: zero counts ----------
__global__ void k_zero_cnt(int n) {
    int i = blockIdx.x * blockDim.x + threadIdx.x;
    if (i < n) g_cnt[i] = 0;
}

// ---------- K2: histogram of dst ----------
__global__ __launch_bounds__(256)
void k_hist(const int* __restrict__ ei, int E) {
    int e = blockIdx.x * blockDim.x + threadIdx.x;
    if (e < E) atomicAdd(&g_cnt[__ldg(&ei[E + e])], 1);
}

// ---------- K3: per-block exclusive scan ----------
__global__ __launch_bounds__(SCAN_T)
void k_scan_block(int n) {
    __shared__ int wsum[32];
    int t = threadIdx.x, b = blockIdx.x;
    int i = b * SCAN_T + t;
    int lane = t & 31, w = t >> 5;

    int v = (i < n) ? g_cnt[i] : 0;
    int incl = v;
    #pragma unroll
    for (int d = 1; d < 32; d <<= 1) {
        int u = __shfl_up_sync(0xffffffffu, incl, d);
        if (lane >= d) incl += u;
    }
    if (lane == 31) wsum[w] = incl;
    __syncthreads();
    if (t < 32) {
        int s = wsum[t];
        int inc2 = s;
        #pragma unroll
        for (int d = 1; d < 32; d <<= 1) {
            int u = __shfl_up_sync(0xffffffffu, inc2, d);
            if (t >= d) inc2 += u;
        }
        wsum[t] = inc2 - s;            // exclusive warp offset
        if (t == 31) g_bsum[b] = inc2; // block total
    }
    __syncthreads();
    int excl = wsum[w] + incl - v;
    if (i < n) g_off[i] = excl;
}

// ---------- K4: add block prefixes, init cursors, set off[n] ----------
__global__ __launch_bounds__(SCAN_T)
void k_scan_final(int n, int nb) {
    __shared__ int pre;
    int t = threadIdx.x, b = blockIdx.x;
    if (t == 0) {
        int s = 0;
        for (int j = 0; j < b; j++) s += g_bsum[j];
        pre = s;
        if (b == 0) {
            int tot = 0;
            for (int j = 0; j < nb; j++) tot += g_bsum[j];
            g_off[n] = tot;
        }
    }
    __syncthreads();
    int i = b * SCAN_T + t;
    if (i < n) {
        int o = g_off[i] + pre;
        g_off[i] = o;
        g_cur[i] = o;
    }
}

// ---------- K5: permute edges into dst buckets ----------
__global__ __launch_bounds__(256)
void k_permute(const int* __restrict__ ei, const float* __restrict__ ew, int E) {
    int e = blockIdx.x * blockDim.x + threadIdx.x;
    if (e >= E) return;
    int s = __ldg(&ei[e]);
    int d = __ldg(&ei[E + e]);
    float w = __ldg(&ew[e]);
    int pos = atomicAdd(&g_cur[d], 1);
    g_rec[pos] = ((unsigned long long)__float_as_uint(w) << 32) | (unsigned)s;
}

// ---------- K6: per-node gather, warp per node ----------
__global__ __launch_bounds__(256)
void k_gather(const float* __restrict__ x, const float* __restrict__ w_mp,
              float* __restrict__ out, int n) {
    int node = (blockIdx.x * blockDim.x + threadIdx.x) >> 5;
    if (node >= n) return;
    int lane = threadIdx.x & 31;
    int slot = lane >> 3;   // which of 4 concurrent edges
    int c    = lane & 7;    // float4 chunk within the 32-float row

    int beg = __ldg(&g_off[node]);
    int end = __ldg(&g_off[node + 1]);

    float4 acc = make_float4(0.f, 0.f, 0.f, 0.f);
    for (int k = beg + slot; k < end; k += 4) {
        unsigned long long r = __ldg(&g_rec[k]);
        float w  = __uint_as_float((unsigned)(r >> 32));
        int  src = (int)(unsigned)r;
        float4 v = __ldg(reinterpret_cast<const float4*>(x + (size_t)src * 32) + c);
        acc.x += w * v.x; acc.y += w * v.y; acc.z += w * v.z; acc.w += w * v.w;
    }
    // reduce the 4 edge-slots (lanes c, c+8, c+16, c+24)
    #pragma unroll
    for (int m = 8; m <= 16; m <<= 1) {
        acc.x += __shfl_xor_sync(0xffffffffu, acc.x, m);
        acc.y += __shfl_xor_sync(0xffffffffu, acc.y, m);
        acc.z += __shfl_xor_sync(0xffffffffu, acc.z, m);
        acc.w += __shfl_xor_sync(0xffffffffu, acc.w, m);
    }
    if (slot == 0) {
        float wm = __ldg(w_mp);
        acc.x *= wm; acc.y *= wm; acc.z *= wm; acc.w *= wm;
        reinterpret_cast<float4*>(out + (size_t)node * 32)[c] = acc;
    }
}

// ---------- Fallback (proven round-4 path) ----------
__global__ void k_zero_out(float4* __restrict__ out, int n4) {
    int i = blockIdx.x * blockDim.x + threadIdx.x;
    if (i < n4) out[i] = make_float4(0.f, 0.f, 0.f, 0.f);
}

__global__ __launch_bounds__(256)
void k_scatter_atomic(const float* __restrict__ x, const int* __restrict__ ei,
                      const float* __restrict__ ew, const float* __restrict__ w_mp,
                      float* __restrict__ out, int E) {
    int tid = blockIdx.x * blockDim.x + threadIdx.x;
    int e = tid >> 3, c = tid & 7;
    if (e >= E) return;
    int s = __ldg(&ei[e]);
    int d = __ldg(&ei[E + e]);
    float w = __ldg(&ew[e]) * __ldg(w_mp);
    float4 v = __ldg(reinterpret_cast<const float4*>(x + (size_t)s * 32) + c);
    v.x *= w; v.y *= w; v.z *= w; v.w *= w;
    float* dst = out + (size_t)d * 32 + c * 4;
    asm volatile("red.global.add.v4.f32 [%0], {%1, %2, %3, %4};"
                 :: "l"(dst), "f"(v.x), "f"(v.y), "f"(v.z), "f"(v.w)
                 : "memory");
}

extern "C" void kernel_launch(void* const* d_in, const int* in_sizes, int n_in,
                              void* d_out, int out_size) {
    const float* x    = (const float*)d_in[0];
    const int*   ei   = (const int*)d_in[1];
    const float* ew   = (const float*)d_in[2];
    const float* w_mp = (const float*)d_in[3];
    float* out = (float*)d_out;

    int E = in_sizes[2];
    int n = out_size / 32;   // nodes

    if (n <= N_MAX && E <= E_MAX) {
        int nb = (n + SCAN_T - 1) / SCAN_T;
        int eb = (E + 255) / 256;
        k_zero_cnt<<<(n + 255) / 256, 256>>>(n);
        k_hist<<<eb, 256>>>(ei, E);
        k_scan_block<<<nb, SCAN_T>>>(n);
        k_scan_final<<<nb, SCAN_T>>>(n, nb);
        k_permute<<<eb, 256>>>(ei, ew, E);
        k_gather<<<(n * 32 + 255) / 256, 256>>>(x, w_mp, out, n);
    } else {
        int n4 = out_size / 4;
        k_zero_out<<<(n4 + 255) / 256, 256>>>((float4*)out, n4);
        long long threads = (long long)E * 8;
        k_scatter_atomic<<<(int)((threads + 255) / 256), 256>>>(x, ei, ew, w_mp, out, E);
    }
}

// round 7
// speedup vs baseline: 1.3218x; 1.3218x over previous
#include <cuda_runtime.h>
#include <cstdint>

// out[n] = w_mp * sum_{e : dst[e]==n} ew[e] * x[src[e]]
// x: [N,32] f32, edge_index: [2,E] int32, ew: [E] f32, w_mp: [1] f32
//
// One-pass fixed-capacity bucketing (no hist/scan), then per-node register
// gather. Eliminates the 12.8M RED.v4 wavefronts that bound the atomic path.

#define N_MAX 120000
#define CAP   64          // slots per node bucket (Poisson(16): P(deg>=64)~1e-25)
#define SPILL_MAX 4096

__device__ int g_cnt[N_MAX];
__device__ unsigned long long g_rec[(size_t)N_MAX * CAP]; // (bits(ew)<<32)|src
__device__ int g_spill_cnt;
__device__ int g_spill[SPILL_MAX];

// ---------- K1: zero counters ----------
__global__ void k_zero_cnt(int n) {
    int i = blockIdx.x * blockDim.x + threadIdx.x;
    if (i < n) g_cnt[i] = 0;
    if (i == 0) g_spill_cnt = 0;
}

// ---------- K2: one-pass bucket permute ----------
__global__ __launch_bounds__(256)
void k_permute(const int* __restrict__ ei, const float* __restrict__ ew, int E) {
    int e = blockIdx.x * blockDim.x + threadIdx.x;
    if (e >= E) return;
    int s = __ldg(&ei[e]);
    int d = __ldg(&ei[E + e]);
    float w = __ldg(&ew[e]);
    int pos = atomicAdd(&g_cnt[d], 1);
    if (pos < CAP) {
        g_rec[(size_t)d * CAP + pos] =
            ((unsigned long long)__float_as_uint(w) << 32) | (unsigned)s;
    } else {
        int sp = atomicAdd(&g_spill_cnt, 1);
        if (sp < SPILL_MAX) g_spill[sp] = e;
    }
}

// ---------- K3: per-node gather, warp per node ----------
__global__ __launch_bounds__(256)
void k_gather(const float* __restrict__ x, const float* __restrict__ w_mp,
              float* __restrict__ out, int n) {
    int node = (blockIdx.x * blockDim.x + threadIdx.x) >> 5;
    if (node >= n) return;
    int lane = threadIdx.x & 31;
    int slot = lane >> 3;   // 4 concurrent edges
    int c    = lane & 7;    // float4 chunk of the 32-float row

    int cnt = __ldg(&g_cnt[node]);
    if (cnt > CAP) cnt = CAP;
    const unsigned long long* rec = g_rec + (size_t)node * CAP;

    float4 acc = make_float4(0.f, 0.f, 0.f, 0.f);
    for (int k = slot; k < cnt; k += 4) {
        unsigned long long r = __ldg(&rec[k]);
        float w  = __uint_as_float((unsigned)(r >> 32));
        int  src = (int)(unsigned)r;
        float4 v = __ldg(reinterpret_cast<const float4*>(x + (size_t)src * 32) + c);
        acc.x += w * v.x; acc.y += w * v.y; acc.z += w * v.z; acc.w += w * v.w;
    }
    // reduce the 4 edge-slots (lanes c, c+8, c+16, c+24)
    #pragma unroll
    for (int m = 8; m <= 16; m <<= 1) {
        acc.x += __shfl_xor_sync(0xffffffffu, acc.x, m);
        acc.y += __shfl_xor_sync(0xffffffffu, acc.y, m);
        acc.z += __shfl_xor_sync(0xffffffffu, acc.z, m);
        acc.w += __shfl_xor_sync(0xffffffffu, acc.w, m);
    }
    if (slot == 0) {
        float wm = __ldg(w_mp);
        acc.x *= wm; acc.y *= wm; acc.z *= wm; acc.w *= wm;
        reinterpret_cast<float4*>(out + (size_t)node * 32)[c] = acc;
    }
}

// ---------- K4: apply spilled edges (normally zero work) ----------
__global__ void k_spill_apply(const float* __restrict__ x, const int* __restrict__ ei,
                              const float* __restrict__ ew, const float* __restrict__ w_mp,
                              float* __restrict__ out, int E) {
    int ns = g_spill_cnt;
    if (ns > SPILL_MAX) ns = SPILL_MAX;
    for (int i = threadIdx.x; i < ns; i += blockDim.x) {
        int e = g_spill[i];
        int s = __ldg(&ei[e]);
        int d = __ldg(&ei[E + e]);
        float w = __ldg(&ew[e]) * __ldg(w_mp);
        #pragma unroll
        for (int c = 0; c < 8; c++) {
            float4 v = __ldg(reinterpret_cast<const float4*>(x + (size_t)s * 32) + c);
            float* dst = out + (size_t)d * 32 + c * 4;
            atomicAdd(dst + 0, w * v.x);
            atomicAdd(dst + 1, w * v.y);
            atomicAdd(dst + 2, w * v.z);
            atomicAdd(dst + 3, w * v.w);
        }
    }
}

// ---------- Fallback (proven round-4 path) ----------
__global__ void k_zero_out(float4* __restrict__ out, int n4) {
    int i = blockIdx.x * blockDim.x + threadIdx.x;
    if (i < n4) out[i] = make_float4(0.f, 0.f, 0.f, 0.f);
}

__global__ __launch_bounds__(256)
void k_scatter_atomic(const float* __restrict__ x, const int* __restrict__ ei,
                      const float* __restrict__ ew, const float* __restrict__ w_mp,
                      float* __restrict__ out, int E) {
    int tid = blockIdx.x * blockDim.x + threadIdx.x;
    int e = tid >> 3, c = tid & 7;
    if (e >= E) return;
    int s = __ldg(&ei[e]);
    int d = __ldg(&ei[E + e]);
    float w = __ldg(&ew[e]) * __ldg(w_mp);
    float4 v = __ldg(reinterpret_cast<const float4*>(x + (size_t)s * 32) + c);
    v.x *= w; v.y *= w; v.z *= w; v.w *= w;
    float* dst = out + (size_t)d * 32 + c * 4;
    asm volatile("red.global.add.v4.f32 [%0], {%1, %2, %3, %4};"
                 :: "l"(dst), "f"(v.x), "f"(v.y), "f"(v.z), "f"(v.w)
                 : "memory");
}

extern "C" void kernel_launch(void* const* d_in, const int* in_sizes, int n_in,
                              void* d_out, int out_size) {
    const float* x    = (const float*)d_in[0];
    const int*   ei   = (const int*)d_in[1];
    const float* ew   = (const float*)d_in[2];
    const float* w_mp = (const float*)d_in[3];
    float* out = (float*)d_out;

    int E = in_sizes[2];
    int n = out_size / 32;   // nodes

    if (n <= N_MAX) {
        int eb = (E + 255) / 256;
        k_zero_cnt<<<(n + 255) / 256, 256>>>(n);
        k_permute<<<eb, 256>>>(ei, ew, E);
        k_gather<<<(n * 32 + 255) / 256, 256>>>(x, w_mp, out, n);
        k_spill_apply<<<1, 256>>>(x, ei, ew, w_mp, out, E);
    } else {
        int n4 = out_size / 4;
        k_zero_out<<<(n4 + 255) / 256, 256>>>((float4*)out, n4);
        long long threads = (long long)E * 8;
        k_scatter_atomic<<<(int)((threads + 255) / 256), 256>>>(x, ei, ew, w_mp, out, E);
    }
}

// round 8
// speedup vs baseline: 1.3772x; 1.0419x over previous
#include <cuda_runtime.h>
#include <cstdint>

// out[n] = w_mp * sum_{e : dst[e]==n} ew[e] * x[src[e]]
// x: [N,32] f32, edge_index: [2,E] int32, ew: [E] f32, w_mp: [1] f32
//
// Two-launch pipeline: bucket-permute -> per-node register gather.
// Counters are self-resetting (zero-init at load; gather restores zeros),
// so no zeroing kernel and no spill-apply kernel.

#define N_MAX 120000
#define CAP   64          // Poisson(16): P(deg>=64) ~ 1e-19 per node
#define SPILL_MAX 4096

__device__ int g_cnt[N_MAX];                               // zero-init
__device__ unsigned long long g_rec[(size_t)N_MAX * CAP];  // (bits(ew)<<32)|src
__device__ int g_spill_cnt;                                // zero-init
__device__ int g_spill_dst[SPILL_MAX];
__device__ unsigned long long g_spill_rec[SPILL_MAX];

// ---------- K1: one-pass bucket permute (2 edges/thread) ----------
__device__ __forceinline__ void permute_one(int s, int d, float w) {
    int pos = atomicAdd(&g_cnt[d], 1);
    unsigned long long r =
        ((unsigned long long)__float_as_uint(w) << 32) | (unsigned)s;
    if (pos < CAP) {
        g_rec[(size_t)d * CAP + pos] = r;
    } else {
        int sp = atomicAdd(&g_spill_cnt, 1);
        if (sp < SPILL_MAX) { g_spill_dst[sp] = d; g_spill_rec[sp] = r; }
    }
}

__global__ __launch_bounds__(256)
void k_permute(const int* __restrict__ ei, const float* __restrict__ ew, int E) {
    int t = blockIdx.x * blockDim.x + threadIdx.x;
    int e = t * 2;
    if (e + 1 < E) {
        int2   s2 = __ldg(reinterpret_cast<const int2*>(ei + e));
        int2   d2 = __ldg(reinterpret_cast<const int2*>(ei + E + e));
        float2 w2 = __ldg(reinterpret_cast<const float2*>(ew + e));
        permute_one(s2.x, d2.x, w2.x);
        permute_one(s2.y, d2.y, w2.y);
    } else if (e < E) {
        permute_one(__ldg(&ei[e]), __ldg(&ei[E + e]), __ldg(&ew[e]));
    }
}

// ---------- K2: per-node gather, warp per node; resets counters ----------
__global__ __launch_bounds__(256)
void k_gather(const float* __restrict__ x, const float* __restrict__ w_mp,
              float* __restrict__ out, int n) {
    int node = (blockIdx.x * blockDim.x + threadIdx.x) >> 5;
    if (node >= n) return;
    int lane = threadIdx.x & 31;
    int slot = lane >> 3;   // 4 concurrent edges
    int c    = lane & 7;    // float4 chunk of the 32-float row

    int raw_cnt = __ldg(&g_cnt[node]);
    int spills  = (raw_cnt > CAP) ? g_spill_cnt : 0;   // ~always 0
    int cnt = raw_cnt > CAP ? CAP : raw_cnt;
    const unsigned long long* rec = g_rec + (size_t)node * CAP;

    float4 acc = make_float4(0.f, 0.f, 0.f, 0.f);
    for (int k = slot; k < cnt; k += 4) {
        unsigned long long r = __ldg(&rec[k]);
        float w  = __uint_as_float((unsigned)(r >> 32));
        int  src = (int)(unsigned)r;
        float4 v = __ldg(reinterpret_cast<const float4*>(x + (size_t)src * 32) + c);
        acc.x += w * v.x; acc.y += w * v.y; acc.z += w * v.z; acc.w += w * v.w;
    }

    // Spill path (cold; only for an overflowing node). Slot 0's 8 lanes scan.
    if (spills > 0 && slot == 0) {
        if (spills > SPILL_MAX) spills = SPILL_MAX;
        for (int i = 0; i < spills; i++) {
            if (g_spill_dst[i] == node) {
                unsigned long long r = g_spill_rec[i];
                float w  = __uint_as_float((unsigned)(r >> 32));
                int  src = (int)(unsigned)r;
                float4 v = __ldg(reinterpret_cast<const float4*>(x + (size_t)src * 32) + c);
                acc.x += w * v.x; acc.y += w * v.y; acc.z += w * v.z; acc.w += w * v.w;
            }
        }
    }

    // reduce the 4 edge-slots (lanes c, c+8, c+16, c+24)
    #pragma unroll
    for (int m = 8; m <= 16; m <<= 1) {
        acc.x += __shfl_xor_sync(0xffffffffu, acc.x, m);
        acc.y += __shfl_xor_sync(0xffffffffu, acc.y, m);
        acc.z += __shfl_xor_sync(0xffffffffu, acc.z, m);
        acc.w += __shfl_xor_sync(0xffffffffu, acc.w, m);
    }

    if (slot == 0) {
        float wm = __ldg(w_mp);
        acc.x *= wm; acc.y *= wm; acc.z *= wm; acc.w *= wm;
        reinterpret_cast<float4*>(out + (size_t)node * 32)[c] = acc;
    }

    // Restore zero-state invariant for the next call (graph replay safe).
    if (lane == 0) g_cnt[node] = 0;
    if (node == 0 && lane == 1) g_spill_cnt = 0;
}

// ---------- Fallback (proven round-4 path) ----------
__global__ void k_zero_out(float4* __restrict__ out, int n4) {
    int i = blockIdx.x * blockDim.x + threadIdx.x;
    if (i < n4) out[i] = make_float4(0.f, 0.f, 0.f, 0.f);
}

__global__ __launch_bounds__(256)
void k_scatter_atomic(const float* __restrict__ x, const int* __restrict__ ei,
                      const float* __restrict__ ew, const float* __restrict__ w_mp,
                      float* __restrict__ out, int E) {
    int tid = blockIdx.x * blockDim.x + threadIdx.x;
    int e = tid >> 3, c = tid & 7;
    if (e >= E) return;
    int s = __ldg(&ei[e]);
    int d = __ldg(&ei[E + e]);
    float w = __ldg(&ew[e]) * __ldg(w_mp);
    float4 v = __ldg(reinterpret_cast<const float4*>(x + (size_t)s * 32) + c);
    v.x *= w; v.y *= w; v.z *= w; v.w *= w;
    float* dst = out + (size_t)d * 32 + c * 4;
    asm volatile("red.global.add.v4.f32 [%0], {%1, %2, %3, %4};"
                 :: "l"(dst), "f"(v.x), "f"(v.y), "f"(v.z), "f"(v.w)
                 : "memory");
}

extern "C" void kernel_launch(void* const* d_in, const int* in_sizes, int n_in,
                              void* d_out, int out_size) {
    const float* x    = (const float*)d_in[0];
    const int*   ei   = (const int*)d_in[1];
    const float* ew   = (const float*)d_in[2];
    const float* w_mp = (const float*)d_in[3];
    float* out = (float*)d_out;

    int E = in_sizes[2];
    int n = out_size / 32;   // nodes

    if (n <= N_MAX) {
        int pt = (E + 1) / 2;                       // 2 edges per thread
        k_permute<<<(pt + 255) / 256, 256>>>(ei, ew, E);
        k_gather<<<(n * 32 + 255) / 256, 256>>>(x, w_mp, out, n);
    } else {
        int n4 = out_size / 4;
        k_zero_out<<<(n4 + 255) / 256, 256>>>((float4*)out, n4);
        long long threads = (long long)E * 8;
        k_scatter_atomic<<<(int)((threads + 255) / 256), 256>>>(x, ei, ew, w_mp, out, E);
    }
}